// round 15
// baseline (speedup 1.0000x reference)
#include <cuda_runtime.h>
#include <cuda_fp16.h>
#include <cstdint>

#define Bb 16
#define NN 577
#define NP 640
#define CC 768
#define HH 12
#define HD 64
#define BH (Bb*HH)          // 192
#define MX (Bb*NN)          // 9232
#define SCALE 0.125f

// ---- fp16/fp32 scratch (static device arrays; pads stay zero) ----
static __device__ __half g_xh[(size_t)MX*CC];
static __device__ __half g_wq[(size_t)CC*CC];
static __device__ __half g_wk[(size_t)CC*CC];
static __device__ __half g_wv[(size_t)CC*CC];
static __device__ __half g_wp[(size_t)CC*CC];
static __device__ __half g_q [(size_t)BH*NP*HD];   // [bh][tok][d], q pre-scaled
static __device__ __half g_k [(size_t)BH*NP*HD];
static __device__ __half g_v [(size_t)BH*NP*HD];
static __device__ __half g_Yh[(size_t)BH*NP*HD];   // A@v fp16 [bh][tok][d]
static __device__ float  g_Yf[(size_t)BH*NP*HD];   // A@v fp32 (for epilogue)
static __device__ float  g_mpl[(size_t)BH*NP];     // rowwise m + ln(l)
static __device__ __half g_hb[(size_t)MX*CC];      // merged-head (b,n,c)

// ======================== low-level helpers (sm_80+ PTX) ========================
__device__ __forceinline__ uint32_t sptr(const void* p){
    return (uint32_t)__cvta_generic_to_shared(p);
}
__device__ __forceinline__ void cpa16(uint32_t dst, const void* src){
    asm volatile("cp.async.cg.shared.global [%0], [%1], 16;\n" :: "r"(dst), "l"(src));
}
#define CP_COMMIT() asm volatile("cp.async.commit_group;\n" ::)
#define CP_WAIT0()  asm volatile("cp.async.wait_group 0;\n" ::)
#define CP_WAIT1()  asm volatile("cp.async.wait_group 1;\n" ::)

__device__ __forceinline__ void ldm4(uint32_t& r0, uint32_t& r1, uint32_t& r2, uint32_t& r3, uint32_t a){
    asm volatile("ldmatrix.sync.aligned.m8n8.x4.shared.b16 {%0,%1,%2,%3}, [%4];"
        : "=r"(r0), "=r"(r1), "=r"(r2), "=r"(r3) : "r"(a));
}
__device__ __forceinline__ void ldm4t(uint32_t& r0, uint32_t& r1, uint32_t& r2, uint32_t& r3, uint32_t a){
    asm volatile("ldmatrix.sync.aligned.m8n8.x4.trans.shared.b16 {%0,%1,%2,%3}, [%4];"
        : "=r"(r0), "=r"(r1), "=r"(r2), "=r"(r3) : "r"(a));
}
__device__ __forceinline__ void mma16(float* c, const uint32_t* a, const uint32_t* b){
    asm volatile("mma.sync.aligned.m16n8k16.row.col.f32.f16.f16.f32 "
        "{%0,%1,%2,%3}, {%4,%5,%6,%7}, {%8,%9}, {%0,%1,%2,%3};"
        : "+f"(c[0]), "+f"(c[1]), "+f"(c[2]), "+f"(c[3])
        : "r"(a[0]), "r"(a[1]), "r"(a[2]), "r"(a[3]), "r"(b[0]), "r"(b[1]));
}
__device__ __forceinline__ uint32_t packh2(float lo, float hi){
    __half2 h = __floats2half2_rn(lo, hi);
    return *reinterpret_cast<uint32_t*>(&h);
}
__device__ __forceinline__ float2 h2f(uint32_t u){
    return __half22float2(*reinterpret_cast<__half2*>(&u));
}

// ======================== fp16 NT GEMM, 3-stage pipeline (round-12 proven) =====
#define GST 20480
#define GEMM_SMEM 61440

__device__ __forceinline__ void gemm_nt_h(
    const __half* __restrict__ A, int ldA, int a_r0, int a_clamp,
    const __half* __restrict__ B, int ldB, int b_r0,
    int Ktot, __half* sm, float (&acc)[2][8][4], int tid)
{
    const int lane = tid & 31, wid = tid >> 5;
    const int wm = wid >> 1, wn = wid & 1;
    const uint32_t s0 = sptr(sm);
    const int T = Ktot / 32;

    auto load = [&](int kt){
        uint32_t base = s0 + (kt % 3) * GST;
        int k0 = kt * 32;
#pragma unroll
        for (int i = 0; i < 2; i++){
            int e = tid + i*256;
            int r = e >> 2, c = e & 3;
            int gr = a_r0 + r; if (a_clamp) gr = (gr < a_clamp) ? gr : (a_clamp - 1);
            cpa16(base + r*80 + c*16, A + (size_t)gr*ldA + k0 + c*8);
        }
#pragma unroll
        for (int i = 0; i < 2; i++){
            int e = tid + i*256;
            int r = e >> 2, c = e & 3;
            cpa16(base + 10240 + r*80 + c*16, B + (size_t)(b_r0 + r)*ldB + k0 + c*8);
        }
        CP_COMMIT();
    };

    load(0);
    if (T > 1) load(1);
    for (int kt = 0; kt < T; kt++){
        if (kt + 1 < T) CP_WAIT1(); else CP_WAIT0();
        __syncthreads();
        if (kt + 2 < T) load(kt + 2);
        uint32_t aB = s0 + (kt % 3) * GST;
        uint32_t bB = aB + 10240;
#pragma unroll
        for (int kf = 0; kf < 2; kf++){
            uint32_t af[2][4], bf[8][2];
#pragma unroll
            for (int mt = 0; mt < 2; mt++){
                uint32_t a = aB + ((wm*32 + mt*16 + (lane & 15))*40 + kf*16 + (lane >> 4)*8)*2;
                ldm4(af[mt][0], af[mt][1], af[mt][2], af[mt][3], a);
            }
#pragma unroll
            for (int p = 0; p < 4; p++){
                uint32_t a = bB + ((wn*64 + p*16 + (lane & 7) + ((lane >> 4) & 1)*8)*40
                                   + kf*16 + ((lane >> 3) & 1)*8)*2;
                ldm4(bf[2*p][0], bf[2*p][1], bf[2*p+1][0], bf[2*p+1][1], a);
            }
#pragma unroll
            for (int mt = 0; mt < 2; mt++)
#pragma unroll
                for (int nf = 0; nf < 8; nf++)
                    mma16(acc[mt][nf], af[mt], bf[nf]);
        }
    }
    __syncthreads();
}

// ======================== kernels ========================
#define NX8 (MX*CC/8)
#define NW8 (CC*CC/8)
#define NCVT (NX8 + 4*NW8)

__global__ void __launch_bounds__(256) k_cvt_all(
    const float* __restrict__ x,  const float* __restrict__ wq,
    const float* __restrict__ wk, const float* __restrict__ wv,
    const float* __restrict__ wp)
{
    int i = blockIdx.x*256 + threadIdx.x;
    if (i >= NCVT) return;
    const float* s; __half* d; int off;
    if (i < NX8){ s = x; d = g_xh; off = i; }
    else {
        int j = i - NX8, w = j / NW8; off = j - w*NW8;
        s = (w == 0) ? wq : (w == 1) ? wk : (w == 2) ? wv : wp;
        d = (w == 0) ? g_wq : (w == 1) ? g_wk : (w == 2) ? g_wv : g_wp;
    }
    const float4* s4 = (const float4*)s;
    float4 a = s4[2*off], b = s4[2*off+1];
    uint4 o;
    o.x = packh2(a.x, a.y); o.y = packh2(a.z, a.w);
    o.z = packh2(b.x, b.y); o.w = packh2(b.z, b.w);
    ((uint4*)d)[off] = o;
}

// K1: QKV projection (NT), outputs [bh][tok][d] fp16, smem-staged coalesced
// epilogue (stride 136 halves, conflict-free). grid (6, 73, 3)
#define SQ 136
__global__ void __launch_bounds__(256) k_qkv(){
    extern __shared__ __align__(16) __half dsm[];
    int tid = threadIdx.x, lane = tid & 31, wid = tid >> 5;
    int wm = wid >> 1, wn = wid & 1, g = lane >> 2, t = lane & 3;
    int z = blockIdx.z, m0 = blockIdx.y*128, n0 = blockIdx.x*128;
    const __half* W = (z == 0) ? g_wq : (z == 1) ? g_wk : g_wv;
    __half* dst = (z == 0) ? g_q : (z == 1) ? g_k : g_v;
    float scale = (z == 0) ? SCALE : 1.f;

    float acc[2][8][4] = {};
    gemm_nt_h(g_xh, CC, m0, MX, W, CC, n0, CC, dsm, acc, tid);

#pragma unroll
    for (int mt = 0; mt < 2; mt++)
#pragma unroll
    for (int nf = 0; nf < 8; nf++){
        int col = wn*64 + nf*8 + t*2;
        int row0 = wm*32 + mt*16 + g;
#pragma unroll
        for (int rr = 0; rr < 2; rr++){
            *(uint32_t*)&dsm[(row0 + rr*8)*SQ + col] =
                packh2(acc[mt][nf][rr*2]*scale, acc[mt][nf][rr*2+1]*scale);
        }
    }
    __syncthreads();

#pragma unroll
    for (int i = 0; i < 8; i++){
        int e = tid + i*256;
        int r = e >> 4, c = e & 15;
        int gm = m0 + r;
        if (gm >= MX) continue;
        int b = gm / NN, n = gm - b*NN;
        int col = n0 + c*8, h = col >> 6, d = col & 63;
        *(uint4*)&dst[(((size_t)(b*HH + h))*NP + n)*HD + d] = *(uint4*)&dsm[r*SQ + c*8];
    }
}

// ======================== flash attention core (round-12 proven) ==============
#define QS 72
#define FST 18432
#define TAILB 73728
#define FL_SMEM (18432 + 3*FST + 256)   // 73984 B
#define TKV 9

template<bool FIRST>
__device__ __forceinline__ void flash_core(
    __half* smh, const __half* qg, const __half* kg, const __half* vg,
    float* __restrict__ mpl, int m0, int tid)
{
    const int lane = tid & 31, wid = tid >> 5;     // wid 0..3
    const int g = lane >> 2, t = lane & 3;
    const int wr = wid*32;
    const uint32_t s0 = sptr(smh);
    const uint32_t sq = s0;

    auto loadkv = [&](int kt){
        uint32_t base = s0 + 18432 + (kt % 3) * FST;
        int tok0 = kt * 64;
#pragma unroll
        for (int i = 0; i < 4; i++){
            int e = tid + i*128;
            int r = e >> 3, c = e & 7;
            cpa16(base + r*(QS*2) + c*16,        kg + (size_t)(tok0 + r)*HD + c*8);
            cpa16(base + 9216 + r*(QS*2) + c*16, vg + (size_t)(tok0 + r)*HD + c*8);
        }
        CP_COMMIT();
    };

#pragma unroll
    for (int i = 0; i < 8; i++){
        int e = tid + i*128;
        int r = e >> 3, c = e & 7;
        cpa16(sq + r*(QS*2) + c*16, qg + (size_t)(m0 + r)*HD + c*8);
    }
    if (tid < 8)       cpa16(s0 + TAILB + tid*16,           kg + (size_t)(NN-1)*HD + tid*8);
    else if (tid < 16) cpa16(s0 + TAILB + 128 + (tid-8)*16, vg + (size_t)(NN-1)*HD + (tid-8)*8);
    CP_COMMIT();
    loadkv(0);
    loadkv(1);

    float mplv[2][2];
    if (!FIRST){
#pragma unroll
        for (int mt = 0; mt < 2; mt++){
            mplv[mt][0] = mpl[m0 + wr + mt*16 + g];
            mplv[mt][1] = mpl[m0 + wr + mt*16 + g + 8];
        }
    }

    asm volatile("cp.async.wait_group 2;\n" ::);   // q + tail ready
    __syncthreads();

    auto qaddr = [&](int mt, int kf){
        return sq + ((wr + mt*16 + (lane & 15))*QS + kf*16 + (lane >> 4)*8)*2;
    };

    uint32_t qf[2][4][4];            // persistent only in SECOND pass
    if (!FIRST){
#pragma unroll
        for (int mt = 0; mt < 2; mt++)
#pragma unroll
        for (int kf = 0; kf < 4; kf++)
            ldm4(qf[mt][kf][0], qf[mt][kf][1], qf[mt][kf][2], qf[mt][kf][3], qaddr(mt, kf));
    }

    float mr[2][2], l[2][2];
    float ya[2][8][4];
#pragma unroll
    for (int mt = 0; mt < 2; mt++){
        mr[mt][0] = -1e30f; mr[mt][1] = -1e30f; l[mt][0] = 0.f; l[mt][1] = 0.f;
#pragma unroll
        for (int nf = 0; nf < 8; nf++){
            ya[mt][nf][0]=0; ya[mt][nf][1]=0; ya[mt][nf][2]=0; ya[mt][nf][3]=0;
        }
    }

    for (int kt = 0; kt < TKV; kt++){
        if (kt + 1 < TKV) CP_WAIT1(); else CP_WAIT0();
        __syncthreads();
        if (kt + 2 < TKV) loadkv(kt + 2);
        uint32_t sk = s0 + 18432 + (kt % 3) * FST;
        uint32_t sv = sk + 9216;

        float sa[2][8][4];
#pragma unroll
        for (int mt = 0; mt < 2; mt++)
#pragma unroll
        for (int nf = 0; nf < 8; nf++){
            sa[mt][nf][0]=0; sa[mt][nf][1]=0; sa[mt][nf][2]=0; sa[mt][nf][3]=0;
        }
#pragma unroll
        for (int kf = 0; kf < 4; kf++){
            uint32_t bf[8][2];
#pragma unroll
            for (int p = 0; p < 4; p++){
                uint32_t a = sk + ((p*16 + (lane & 7) + ((lane >> 4) & 1)*8)*QS
                                   + kf*16 + ((lane >> 3) & 1)*8)*2;
                ldm4(bf[2*p][0], bf[2*p][1], bf[2*p+1][0], bf[2*p+1][1], a);
            }
#pragma unroll
            for (int mt = 0; mt < 2; mt++){
                if (FIRST){
                    uint32_t ql[4];
                    ldm4(ql[0], ql[1], ql[2], ql[3], qaddr(mt, kf));
#pragma unroll
                    for (int nf = 0; nf < 8; nf++) mma16(sa[mt][nf], ql, bf[nf]);
                } else {
#pragma unroll
                    for (int nf = 0; nf < 8; nf++) mma16(sa[mt][nf], qf[mt][kf], bf[nf]);
                }
            }
        }

        uint32_t pf[2][4][4];
#pragma unroll
        for (int mt = 0; mt < 2; mt++){
            if (FIRST){
                float tm0 = -1e30f, tm1 = -1e30f;
#pragma unroll
                for (int nf = 0; nf < 8; nf++){
                    tm0 = fmaxf(tm0, fmaxf(sa[mt][nf][0], sa[mt][nf][1]));
                    tm1 = fmaxf(tm1, fmaxf(sa[mt][nf][2], sa[mt][nf][3]));
                }
                tm0 = fmaxf(tm0, __shfl_xor_sync(~0u, tm0, 1));
                tm0 = fmaxf(tm0, __shfl_xor_sync(~0u, tm0, 2));
                tm1 = fmaxf(tm1, __shfl_xor_sync(~0u, tm1, 1));
                tm1 = fmaxf(tm1, __shfl_xor_sync(~0u, tm1, 2));
                float mn0 = fmaxf(mr[mt][0], tm0), mn1 = fmaxf(mr[mt][1], tm1);
                float sc0 = __expf(mr[mt][0] - mn0), sc1 = __expf(mr[mt][1] - mn1);
                mr[mt][0] = mn0; mr[mt][1] = mn1;
                l[mt][0] *= sc0; l[mt][1] *= sc1;
#pragma unroll
                for (int nf = 0; nf < 8; nf++){
                    ya[mt][nf][0] *= sc0; ya[mt][nf][1] *= sc0;
                    ya[mt][nf][2] *= sc1; ya[mt][nf][3] *= sc1;
                }
                float rs0 = 0.f, rs1 = 0.f;
#pragma unroll
                for (int j = 0; j < 4; j++){
                    float p00 = __expf(sa[mt][2*j][0] - mn0),   p01 = __expf(sa[mt][2*j][1] - mn0);
                    float p02 = __expf(sa[mt][2*j][2] - mn1),   p03 = __expf(sa[mt][2*j][3] - mn1);
                    float p10 = __expf(sa[mt][2*j+1][0] - mn0), p11 = __expf(sa[mt][2*j+1][1] - mn0);
                    float p12 = __expf(sa[mt][2*j+1][2] - mn1), p13 = __expf(sa[mt][2*j+1][3] - mn1);
                    rs0 += p00 + p01 + p10 + p11;
                    rs1 += p02 + p03 + p12 + p13;
                    pf[mt][j][0] = packh2(p00, p01);
                    pf[mt][j][1] = packh2(p02, p03);
                    pf[mt][j][2] = packh2(p10, p11);
                    pf[mt][j][3] = packh2(p12, p13);
                }
                rs0 += __shfl_xor_sync(~0u, rs0, 1); rs0 += __shfl_xor_sync(~0u, rs0, 2);
                rs1 += __shfl_xor_sync(~0u, rs1, 1); rs1 += __shfl_xor_sync(~0u, rs1, 2);
                l[mt][0] += rs0; l[mt][1] += rs1;
            } else {
#pragma unroll
                for (int j = 0; j < 4; j++){
                    pf[mt][j][0] = packh2(__expf(sa[mt][2*j][0] - mplv[mt][0]),
                                          __expf(sa[mt][2*j][1] - mplv[mt][0]));
                    pf[mt][j][1] = packh2(__expf(sa[mt][2*j][2] - mplv[mt][1]),
                                          __expf(sa[mt][2*j][3] - mplv[mt][1]));
                    pf[mt][j][2] = packh2(__expf(sa[mt][2*j+1][0] - mplv[mt][0]),
                                          __expf(sa[mt][2*j+1][1] - mplv[mt][0]));
                    pf[mt][j][3] = packh2(__expf(sa[mt][2*j+1][2] - mplv[mt][1]),
                                          __expf(sa[mt][2*j+1][3] - mplv[mt][1]));
                }
            }
        }

#pragma unroll
        for (int kf = 0; kf < 4; kf++){
            uint32_t vf[8][2];
#pragma unroll
            for (int p = 0; p < 4; p++){
                uint32_t a = sv + ((kf*16 + (lane & 7) + ((lane >> 3) & 1)*8)*QS
                                   + p*16 + (lane >> 4)*8)*2;
                ldm4t(vf[2*p][0], vf[2*p][1], vf[2*p+1][0], vf[2*p+1][1], a);
            }
#pragma unroll
            for (int mt = 0; mt < 2; mt++)
#pragma unroll
            for (int nf = 0; nf < 8; nf++)
                mma16(ya[mt][nf], pf[mt][kf], vf[nf]);
        }
    }

    // ---- tail: key 576 (rank-1) ----
    {
        const __half2* kt2 = (const __half2*)(smh + TAILB/2);
        const __half2* vt2 = kt2 + 32;
#pragma unroll
        for (int mt = 0; mt < 2; mt++){
            float s0v = 0.f, s1v = 0.f;
#pragma unroll
            for (int kf = 0; kf < 4; kf++){
                uint32_t q0, q1, q2, q3;
                if (FIRST){
                    ldm4(q0, q1, q2, q3, qaddr(mt, kf));
                } else {
                    q0 = qf[mt][kf][0]; q1 = qf[mt][kf][1];
                    q2 = qf[mt][kf][2]; q3 = qf[mt][kf][3];
                }
                float2 klo = __half22float2(kt2[kf*8 + t]);
                float2 khi = __half22float2(kt2[kf*8 + 4 + t]);
                float2 q0l = h2f(q0), q1l = h2f(q1);
                float2 q0h = h2f(q2), q1h = h2f(q3);
                s0v += q0l.x*klo.x + q0l.y*klo.y + q0h.x*khi.x + q0h.y*khi.y;
                s1v += q1l.x*klo.x + q1l.y*klo.y + q1h.x*khi.x + q1h.y*khi.y;
            }
            s0v += __shfl_xor_sync(~0u, s0v, 1); s0v += __shfl_xor_sync(~0u, s0v, 2);
            s1v += __shfl_xor_sync(~0u, s1v, 1); s1v += __shfl_xor_sync(~0u, s1v, 2);

            if (FIRST){
                float mn0 = fmaxf(mr[mt][0], s0v), mn1 = fmaxf(mr[mt][1], s1v);
                float sc0 = __expf(mr[mt][0] - mn0), sc1 = __expf(mr[mt][1] - mn1);
                float p0 = __expf(s0v - mn0), p1 = __expf(s1v - mn1);
                l[mt][0] = l[mt][0]*sc0 + p0; l[mt][1] = l[mt][1]*sc1 + p1;
#pragma unroll
                for (int nf = 0; nf < 8; nf++){
                    float2 v2 = __half22float2(vt2[nf*4 + t]);
                    ya[mt][nf][0] = ya[mt][nf][0]*sc0 + p0*v2.x;
                    ya[mt][nf][1] = ya[mt][nf][1]*sc0 + p0*v2.y;
                    ya[mt][nf][2] = ya[mt][nf][2]*sc1 + p1*v2.x;
                    ya[mt][nf][3] = ya[mt][nf][3]*sc1 + p1*v2.y;
                }
                if (t == 0){
                    mpl[m0 + wr + mt*16 + g]     = mn0 + __logf(l[mt][0]);
                    mpl[m0 + wr + mt*16 + g + 8] = mn1 + __logf(l[mt][1]);
                }
            } else {
                float p0 = __expf(s0v - mplv[mt][0]), p1 = __expf(s1v - mplv[mt][1]);
#pragma unroll
                for (int nf = 0; nf < 8; nf++){
                    float2 v2 = __half22float2(vt2[nf*4 + t]);
                    ya[mt][nf][0] += p0*v2.x; ya[mt][nf][1] += p0*v2.y;
                    ya[mt][nf][2] += p1*v2.x; ya[mt][nf][3] += p1*v2.y;
                }
            }
        }
    }
    __syncthreads();

    float* st = (float*)smh;
#pragma unroll
    for (int mt = 0; mt < 2; mt++){
        float inv0 = FIRST ? (1.f / l[mt][0]) : 1.f;
        float inv1 = FIRST ? (1.f / l[mt][1]) : 1.f;
#pragma unroll
        for (int nf = 0; nf < 8; nf++){
            int d = nf*8 + t*2;
            st[(wr + mt*16 + g)*68 + d]         = ya[mt][nf][0]*inv0;
            st[(wr + mt*16 + g)*68 + d + 1]     = ya[mt][nf][1]*inv0;
            st[(wr + mt*16 + g + 8)*68 + d]     = ya[mt][nf][2]*inv1;
            st[(wr + mt*16 + g + 8)*68 + d + 1] = ya[mt][nf][3]*inv1;
        }
    }
    __syncthreads();
}

// K2: Y = softmax(qk) @ v -> g_Yh + g_Yf + g_mpl. grid (5, 192), 128 threads
__global__ void __launch_bounds__(128, 3) k_av_f(){
    extern __shared__ __align__(16) __half dsm[];
    int tid = threadIdx.x;
    int m0 = blockIdx.x*128, bh = blockIdx.y;
    size_t ob = (size_t)bh*NP*HD;
    flash_core<true>(dsm, g_q + ob, g_k + ob, g_v + ob, g_mpl + (size_t)bh*NP, m0, tid);

    const float* src = (const float*)dsm + tid*68;
    size_t o = ob + (size_t)(m0 + tid)*HD;
#pragma unroll
    for (int i = 0; i < 16; i++)
        ((float4*)(g_Yf + o))[i] = ((const float4*)src)[i];
#pragma unroll
    for (int i = 0; i < 8; i++){
        uint4 u;
        u.x = packh2(src[i*8+0], src[i*8+1]);
        u.y = packh2(src[i*8+2], src[i*8+3]);
        u.z = packh2(src[i*8+4], src[i*8+5]);
        u.w = packh2(src[i*8+6], src[i*8+7]);
        ((uint4*)(g_Yh + o))[i] = u;
    }
}

// K3: Z = softmax(qk) @ Y; hb = (1-2b)Y + 3b*Z. grid (5, 192), 128 threads
__global__ void __launch_bounds__(128, 3) k_ay_f(const float* __restrict__ lamb){
    extern __shared__ __align__(16) __half dsm[];
    int tid = threadIdx.x;
    int m0 = blockIdx.x*128, bh = blockIdx.y;
    int b = bh / HH, h = bh - b*HH;
    size_t ob = (size_t)bh*NP*HD;
    flash_core<false>(dsm, g_q + ob, g_k + ob, g_Yh + ob, g_mpl + (size_t)bh*NP, m0, tid);

    float beta = lamb[h];
    float c0 = 1.f - 2.f*beta, c1 = 3.f*beta;
    int tok = m0 + tid;
    if (tok < NN){
        const float* zs = (const float*)dsm + tid*68;
        const float* yf = g_Yf + ob + (size_t)tok*HD;
        __half* dst = g_hb + ((size_t)(b*NN + tok))*CC + h*64;
#pragma unroll
        for (int i = 0; i < 8; i++){
            uint4 u;
            u.x = packh2(c0*yf[i*8+0] + c1*zs[i*8+0], c0*yf[i*8+1] + c1*zs[i*8+1]);
            u.y = packh2(c0*yf[i*8+2] + c1*zs[i*8+2], c0*yf[i*8+3] + c1*zs[i*8+3]);
            u.z = packh2(c0*yf[i*8+4] + c1*zs[i*8+4], c0*yf[i*8+5] + c1*zs[i*8+5]);
            u.w = packh2(c0*yf[i*8+6] + c1*zs[i*8+6], c0*yf[i*8+7] + c1*zs[i*8+7]);
            ((uint4*)dst)[i] = u;
        }
    }
}

// K4: out = hb @ Wp^T + bp (NT, fp32 out), smem-staged coalesced epilogue.
// Staging: 128 x 132 fp32 (67,584 B; > mainloop's 61,440 -> smem = 67,584).
// grid (6, 73)
#define SP 132
#define PROJ_SMEM (128*SP*4)   // 67584
__global__ void __launch_bounds__(256)
k_proj(const float* __restrict__ bp, float* __restrict__ out){
    extern __shared__ __align__(16) __half dsm[];
    int tid = threadIdx.x, lane = tid & 31, wid = tid >> 5;
    int wm = wid >> 1, wn = wid & 1, g = lane >> 2, t = lane & 3;
    int m0 = blockIdx.y*128, n0 = blockIdx.x*128;

    float acc[2][8][4] = {};
    gemm_nt_h(g_hb, CC, m0, MX, g_wp, CC, n0, CC, dsm, acc, tid);

    // stage fp32 tile with bias added
    float* st = (float*)dsm;
#pragma unroll
    for (int mt = 0; mt < 2; mt++)
#pragma unroll
    for (int nf = 0; nf < 8; nf++){
        int col = wn*64 + nf*8 + t*2;
        float b0 = bp[n0 + col], b1 = bp[n0 + col + 1];
        int row0 = wm*32 + mt*16 + g;
#pragma unroll
        for (int rr = 0; rr < 2; rr++){
            st[(row0 + rr*8)*SP + col]     = acc[mt][nf][rr*2]   + b0;
            st[(row0 + rr*8)*SP + col + 1] = acc[mt][nf][rr*2+1] + b1;
        }
    }
    __syncthreads();

    // coalesced float4 stores: 32 chunks per row, consecutive tids in a row
#pragma unroll
    for (int i = 0; i < 16; i++){
        int e = tid + i*256;
        int r = e >> 5, c = e & 31;
        int gm = m0 + r;
        if (gm >= MX) continue;
        *(float4*)&out[(size_t)gm*CC + n0 + c*4] = *(const float4*)&st[r*SP + c*4];
    }
}

// ======================== host launcher ========================
extern "C" void kernel_launch(void* const* d_in, const int* in_sizes, int n_in,
                              void* d_out, int out_size)
{
    const float* x    = (const float*)d_in[0];
    const float* Wq   = (const float*)d_in[1];
    const float* Wk   = (const float*)d_in[2];
    const float* Wv   = (const float*)d_in[3];
    const float* Wp   = (const float*)d_in[4];
    const float* bp   = (const float*)d_in[5];
    const float* lamb = (const float*)d_in[6];
    float* out = (float*)d_out;

    static bool attr_done = false;
    if (!attr_done){
        cudaFuncSetAttribute(k_qkv,  cudaFuncAttributeMaxDynamicSharedMemorySize, GEMM_SMEM);
        cudaFuncSetAttribute(k_proj, cudaFuncAttributeMaxDynamicSharedMemorySize, PROJ_SMEM);
        cudaFuncSetAttribute(k_av_f, cudaFuncAttributeMaxDynamicSharedMemorySize, FL_SMEM);
        cudaFuncSetAttribute(k_ay_f, cudaFuncAttributeMaxDynamicSharedMemorySize, FL_SMEM);
        attr_done = true;
    }

    k_cvt_all<<<(NCVT + 255)/256, 256>>>(x, Wq, Wk, Wv, Wp);
    k_qkv <<<dim3(CC/128, (MX + 127)/128, 3), 256, GEMM_SMEM>>>();
    k_av_f<<<dim3(NP/128, BH), 128, FL_SMEM>>>();
    k_ay_f<<<dim3(NP/128, BH), 128, FL_SMEM>>>(lamb);
    k_proj<<<dim3(CC/128, (MX + 127)/128), 256, PROJ_SMEM>>>(bp, out);
}

// round 16
// speedup vs baseline: 1.0428x; 1.0428x over previous
#include <cuda_runtime.h>
#include <cuda_fp16.h>
#include <cstdint>

#define Bb 16
#define NN 577
#define NP 640
#define CC 768
#define HH 12
#define HD 64
#define BH (Bb*HH)          // 192
#define MX (Bb*NN)          // 9232
#define SCALE 0.125f

// ---- fp16/fp32 scratch (static device arrays; pads stay zero) ----
static __device__ __half g_xh[(size_t)MX*CC];
static __device__ __half g_wq[(size_t)CC*CC];
static __device__ __half g_wk[(size_t)CC*CC];
static __device__ __half g_wv[(size_t)CC*CC];
static __device__ __half g_wp[(size_t)CC*CC];
static __device__ __half g_q [(size_t)BH*NP*HD];   // [bh][tok][d], q pre-scaled
static __device__ __half g_k [(size_t)BH*NP*HD];
static __device__ __half g_v [(size_t)BH*NP*HD];
static __device__ __half g_Yh[(size_t)BH*NP*HD];   // A@v fp16 [bh][tok][d]
static __device__ float  g_Yf[(size_t)BH*NP*HD];   // A@v fp32 (for epilogue)
static __device__ float  g_mpl[(size_t)BH*NP];     // rowwise m + ln(l)
static __device__ __half g_hb[(size_t)MX*CC];      // merged-head (b,n,c)

// ======================== low-level helpers (sm_80+ PTX) ========================
__device__ __forceinline__ uint32_t sptr(const void* p){
    return (uint32_t)__cvta_generic_to_shared(p);
}
__device__ __forceinline__ void cpa16(uint32_t dst, const void* src){
    asm volatile("cp.async.cg.shared.global [%0], [%1], 16;\n" :: "r"(dst), "l"(src));
}
#define CP_COMMIT() asm volatile("cp.async.commit_group;\n" ::)
#define CP_WAIT0()  asm volatile("cp.async.wait_group 0;\n" ::)
#define CP_WAIT1()  asm volatile("cp.async.wait_group 1;\n" ::)

__device__ __forceinline__ void ldm4(uint32_t& r0, uint32_t& r1, uint32_t& r2, uint32_t& r3, uint32_t a){
    asm volatile("ldmatrix.sync.aligned.m8n8.x4.shared.b16 {%0,%1,%2,%3}, [%4];"
        : "=r"(r0), "=r"(r1), "=r"(r2), "=r"(r3) : "r"(a));
}
__device__ __forceinline__ void ldm4t(uint32_t& r0, uint32_t& r1, uint32_t& r2, uint32_t& r3, uint32_t a){
    asm volatile("ldmatrix.sync.aligned.m8n8.x4.trans.shared.b16 {%0,%1,%2,%3}, [%4];"
        : "=r"(r0), "=r"(r1), "=r"(r2), "=r"(r3) : "r"(a));
}
__device__ __forceinline__ void mma16(float* c, const uint32_t* a, const uint32_t* b){
    asm volatile("mma.sync.aligned.m16n8k16.row.col.f32.f16.f16.f32 "
        "{%0,%1,%2,%3}, {%4,%5,%6,%7}, {%8,%9}, {%0,%1,%2,%3};"
        : "+f"(c[0]), "+f"(c[1]), "+f"(c[2]), "+f"(c[3])
        : "r"(a[0]), "r"(a[1]), "r"(a[2]), "r"(a[3]), "r"(b[0]), "r"(b[1]));
}
__device__ __forceinline__ uint32_t packh2(float lo, float hi){
    __half2 h = __floats2half2_rn(lo, hi);
    return *reinterpret_cast<uint32_t*>(&h);
}
__device__ __forceinline__ float2 h2f(uint32_t u){
    return __half22float2(*reinterpret_cast<__half2*>(&u));
}

// ======================== fp16 NT GEMM, 3-stage, 4 warps x (64x64) =============
// 128 threads. Per kf-step each warp: 8 LDSM -> 32 MMAs (ratio 4.0 vs 2.67 in
// the 8-warp 32x64 layout), and per-CTA LDSM traffic drops 1.5x.
#define GST 20480
#define GEMM_SMEM 61440

__device__ __forceinline__ void gemm_nt_h(
    const __half* __restrict__ A, int ldA, int a_r0, int a_clamp,
    const __half* __restrict__ B, int ldB, int b_r0,
    int Ktot, __half* sm, float (&acc)[4][8][4], int tid)
{
    const int lane = tid & 31, wid = tid >> 5;   // wid 0..3
    const int wm = wid >> 1, wn = wid & 1;       // 2x2 warp grid
    const uint32_t s0 = sptr(sm);
    const int T = Ktot / 32;

    auto load = [&](int kt){
        uint32_t base = s0 + (kt % 3) * GST;
        int k0 = kt * 32;
#pragma unroll
        for (int i = 0; i < 4; i++){
            int e = tid + i*128;
            int r = e >> 2, c = e & 3;
            int gr = a_r0 + r; if (a_clamp) gr = (gr < a_clamp) ? gr : (a_clamp - 1);
            cpa16(base + r*80 + c*16, A + (size_t)gr*ldA + k0 + c*8);
        }
#pragma unroll
        for (int i = 0; i < 4; i++){
            int e = tid + i*128;
            int r = e >> 2, c = e & 3;
            cpa16(base + 10240 + r*80 + c*16, B + (size_t)(b_r0 + r)*ldB + k0 + c*8);
        }
        CP_COMMIT();
    };

    load(0);
    if (T > 1) load(1);
    for (int kt = 0; kt < T; kt++){
        if (kt + 1 < T) CP_WAIT1(); else CP_WAIT0();
        __syncthreads();
        if (kt + 2 < T) load(kt + 2);
        uint32_t aB = s0 + (kt % 3) * GST;
        uint32_t bB = aB + 10240;
#pragma unroll
        for (int kf = 0; kf < 2; kf++){
            uint32_t af[4][4], bf[8][2];
#pragma unroll
            for (int mt = 0; mt < 4; mt++){
                uint32_t a = aB + ((wm*64 + mt*16 + (lane & 15))*40 + kf*16 + (lane >> 4)*8)*2;
                ldm4(af[mt][0], af[mt][1], af[mt][2], af[mt][3], a);
            }
#pragma unroll
            for (int p = 0; p < 4; p++){
                uint32_t a = bB + ((wn*64 + p*16 + (lane & 7) + ((lane >> 4) & 1)*8)*40
                                   + kf*16 + ((lane >> 3) & 1)*8)*2;
                ldm4(bf[2*p][0], bf[2*p][1], bf[2*p+1][0], bf[2*p+1][1], a);
            }
#pragma unroll
            for (int mt = 0; mt < 4; mt++)
#pragma unroll
                for (int nf = 0; nf < 8; nf++)
                    mma16(acc[mt][nf], af[mt], bf[nf]);
        }
    }
    __syncthreads();
}

// ======================== kernels ========================
#define NX8 (MX*CC/8)
#define NW8 (CC*CC/8)
#define NCVT (NX8 + 4*NW8)

__global__ void __launch_bounds__(256) k_cvt_all(
    const float* __restrict__ x,  const float* __restrict__ wq,
    const float* __restrict__ wk, const float* __restrict__ wv,
    const float* __restrict__ wp)
{
    int i = blockIdx.x*256 + threadIdx.x;
    if (i >= NCVT) return;
    const float* s; __half* d; int off;
    if (i < NX8){ s = x; d = g_xh; off = i; }
    else {
        int j = i - NX8, w = j / NW8; off = j - w*NW8;
        s = (w == 0) ? wq : (w == 1) ? wk : (w == 2) ? wv : wp;
        d = (w == 0) ? g_wq : (w == 1) ? g_wk : (w == 2) ? g_wv : g_wp;
    }
    const float4* s4 = (const float4*)s;
    float4 a = s4[2*off], b = s4[2*off+1];
    uint4 o;
    o.x = packh2(a.x, a.y); o.y = packh2(a.z, a.w);
    o.z = packh2(b.x, b.y); o.w = packh2(b.z, b.w);
    ((uint4*)d)[off] = o;
}

// K1: QKV projection (NT), 128 threads, smem-staged coalesced epilogue.
// grid (6, 73, 3)
#define SQ 136
__global__ void __launch_bounds__(128) k_qkv(){
    extern __shared__ __align__(16) __half dsm[];
    int tid = threadIdx.x, lane = tid & 31, wid = tid >> 5;
    int wm = wid >> 1, wn = wid & 1, g = lane >> 2, t = lane & 3;
    int z = blockIdx.z, m0 = blockIdx.y*128, n0 = blockIdx.x*128;
    const __half* W = (z == 0) ? g_wq : (z == 1) ? g_wk : g_wv;
    __half* dst = (z == 0) ? g_q : (z == 1) ? g_k : g_v;
    float scale = (z == 0) ? SCALE : 1.f;

    float acc[4][8][4] = {};
    gemm_nt_h(g_xh, CC, m0, MX, W, CC, n0, CC, dsm, acc, tid);

    // stage tile to smem as fp16 (scale applied)
#pragma unroll
    for (int mt = 0; mt < 4; mt++)
#pragma unroll
    for (int nf = 0; nf < 8; nf++){
        int col = wn*64 + nf*8 + t*2;
        int row0 = wm*64 + mt*16 + g;
#pragma unroll
        for (int rr = 0; rr < 2; rr++){
            *(uint32_t*)&dsm[(row0 + rr*8)*SQ + col] =
                packh2(acc[mt][nf][rr*2]*scale, acc[mt][nf][rr*2+1]*scale);
        }
    }
    __syncthreads();

    // coalesced store: 16 chunks of 8 halves per row
#pragma unroll
    for (int i = 0; i < 16; i++){
        int e = tid + i*128;
        int r = e >> 4, c = e & 15;
        int gm = m0 + r;
        if (gm >= MX) continue;
        int b = gm / NN, n = gm - b*NN;
        int col = n0 + c*8, h = col >> 6, d = col & 63;
        *(uint4*)&dst[(((size_t)(b*HH + h))*NP + n)*HD + d] = *(uint4*)&dsm[r*SQ + c*8];
    }
}

// ======================== flash attention core (round-12/15 proven) ===========
#define QS 72
#define FST 18432
#define TAILB 73728
#define FL_SMEM (18432 + 3*FST + 256)   // 73984 B
#define TKV 9

template<bool FIRST>
__device__ __forceinline__ void flash_core(
    __half* smh, const __half* qg, const __half* kg, const __half* vg,
    float* __restrict__ mpl, int m0, int tid)
{
    const int lane = tid & 31, wid = tid >> 5;     // wid 0..3
    const int g = lane >> 2, t = lane & 3;
    const int wr = wid*32;
    const uint32_t s0 = sptr(smh);
    const uint32_t sq = s0;

    auto loadkv = [&](int kt){
        uint32_t base = s0 + 18432 + (kt % 3) * FST;
        int tok0 = kt * 64;
#pragma unroll
        for (int i = 0; i < 4; i++){
            int e = tid + i*128;
            int r = e >> 3, c = e & 7;
            cpa16(base + r*(QS*2) + c*16,        kg + (size_t)(tok0 + r)*HD + c*8);
            cpa16(base + 9216 + r*(QS*2) + c*16, vg + (size_t)(tok0 + r)*HD + c*8);
        }
        CP_COMMIT();
    };

#pragma unroll
    for (int i = 0; i < 8; i++){
        int e = tid + i*128;
        int r = e >> 3, c = e & 7;
        cpa16(sq + r*(QS*2) + c*16, qg + (size_t)(m0 + r)*HD + c*8);
    }
    if (tid < 8)       cpa16(s0 + TAILB + tid*16,           kg + (size_t)(NN-1)*HD + tid*8);
    else if (tid < 16) cpa16(s0 + TAILB + 128 + (tid-8)*16, vg + (size_t)(NN-1)*HD + (tid-8)*8);
    CP_COMMIT();
    loadkv(0);
    loadkv(1);

    float mplv[2][2];
    if (!FIRST){
#pragma unroll
        for (int mt = 0; mt < 2; mt++){
            mplv[mt][0] = mpl[m0 + wr + mt*16 + g];
            mplv[mt][1] = mpl[m0 + wr + mt*16 + g + 8];
        }
    }

    asm volatile("cp.async.wait_group 2;\n" ::);   // q + tail ready
    __syncthreads();

    auto qaddr = [&](int mt, int kf){
        return sq + ((wr + mt*16 + (lane & 15))*QS + kf*16 + (lane >> 4)*8)*2;
    };

    uint32_t qf[2][4][4];            // persistent only in SECOND pass
    if (!FIRST){
#pragma unroll
        for (int mt = 0; mt < 2; mt++)
#pragma unroll
        for (int kf = 0; kf < 4; kf++)
            ldm4(qf[mt][kf][0], qf[mt][kf][1], qf[mt][kf][2], qf[mt][kf][3], qaddr(mt, kf));
    }

    float mr[2][2], l[2][2];
    float ya[2][8][4];
#pragma unroll
    for (int mt = 0; mt < 2; mt++){
        mr[mt][0] = -1e30f; mr[mt][1] = -1e30f; l[mt][0] = 0.f; l[mt][1] = 0.f;
#pragma unroll
        for (int nf = 0; nf < 8; nf++){
            ya[mt][nf][0]=0; ya[mt][nf][1]=0; ya[mt][nf][2]=0; ya[mt][nf][3]=0;
        }
    }

    for (int kt = 0; kt < TKV; kt++){
        if (kt + 1 < TKV) CP_WAIT1(); else CP_WAIT0();
        __syncthreads();
        if (kt + 2 < TKV) loadkv(kt + 2);
        uint32_t sk = s0 + 18432 + (kt % 3) * FST;
        uint32_t sv = sk + 9216;

        float sa[2][8][4];
#pragma unroll
        for (int mt = 0; mt < 2; mt++)
#pragma unroll
        for (int nf = 0; nf < 8; nf++){
            sa[mt][nf][0]=0; sa[mt][nf][1]=0; sa[mt][nf][2]=0; sa[mt][nf][3]=0;
        }
#pragma unroll
        for (int kf = 0; kf < 4; kf++){
            uint32_t bf[8][2];
#pragma unroll
            for (int p = 0; p < 4; p++){
                uint32_t a = sk + ((p*16 + (lane & 7) + ((lane >> 4) & 1)*8)*QS
                                   + kf*16 + ((lane >> 3) & 1)*8)*2;
                ldm4(bf[2*p][0], bf[2*p][1], bf[2*p+1][0], bf[2*p+1][1], a);
            }
#pragma unroll
            for (int mt = 0; mt < 2; mt++){
                if (FIRST){
                    uint32_t ql[4];
                    ldm4(ql[0], ql[1], ql[2], ql[3], qaddr(mt, kf));
#pragma unroll
                    for (int nf = 0; nf < 8; nf++) mma16(sa[mt][nf], ql, bf[nf]);
                } else {
#pragma unroll
                    for (int nf = 0; nf < 8; nf++) mma16(sa[mt][nf], qf[mt][kf], bf[nf]);
                }
            }
        }

        uint32_t pf[2][4][4];
#pragma unroll
        for (int mt = 0; mt < 2; mt++){
            if (FIRST){
                float tm0 = -1e30f, tm1 = -1e30f;
#pragma unroll
                for (int nf = 0; nf < 8; nf++){
                    tm0 = fmaxf(tm0, fmaxf(sa[mt][nf][0], sa[mt][nf][1]));
                    tm1 = fmaxf(tm1, fmaxf(sa[mt][nf][2], sa[mt][nf][3]));
                }
                tm0 = fmaxf(tm0, __shfl_xor_sync(~0u, tm0, 1));
                tm0 = fmaxf(tm0, __shfl_xor_sync(~0u, tm0, 2));
                tm1 = fmaxf(tm1, __shfl_xor_sync(~0u, tm1, 1));
                tm1 = fmaxf(tm1, __shfl_xor_sync(~0u, tm1, 2));
                float mn0 = fmaxf(mr[mt][0], tm0), mn1 = fmaxf(mr[mt][1], tm1);
                float sc0 = __expf(mr[mt][0] - mn0), sc1 = __expf(mr[mt][1] - mn1);
                mr[mt][0] = mn0; mr[mt][1] = mn1;
                l[mt][0] *= sc0; l[mt][1] *= sc1;
#pragma unroll
                for (int nf = 0; nf < 8; nf++){
                    ya[mt][nf][0] *= sc0; ya[mt][nf][1] *= sc0;
                    ya[mt][nf][2] *= sc1; ya[mt][nf][3] *= sc1;
                }
                float rs0 = 0.f, rs1 = 0.f;
#pragma unroll
                for (int j = 0; j < 4; j++){
                    float p00 = __expf(sa[mt][2*j][0] - mn0),   p01 = __expf(sa[mt][2*j][1] - mn0);
                    float p02 = __expf(sa[mt][2*j][2] - mn1),   p03 = __expf(sa[mt][2*j][3] - mn1);
                    float p10 = __expf(sa[mt][2*j+1][0] - mn0), p11 = __expf(sa[mt][2*j+1][1] - mn0);
                    float p12 = __expf(sa[mt][2*j+1][2] - mn1), p13 = __expf(sa[mt][2*j+1][3] - mn1);
                    rs0 += p00 + p01 + p10 + p11;
                    rs1 += p02 + p03 + p12 + p13;
                    pf[mt][j][0] = packh2(p00, p01);
                    pf[mt][j][1] = packh2(p02, p03);
                    pf[mt][j][2] = packh2(p10, p11);
                    pf[mt][j][3] = packh2(p12, p13);
                }
                rs0 += __shfl_xor_sync(~0u, rs0, 1); rs0 += __shfl_xor_sync(~0u, rs0, 2);
                rs1 += __shfl_xor_sync(~0u, rs1, 1); rs1 += __shfl_xor_sync(~0u, rs1, 2);
                l[mt][0] += rs0; l[mt][1] += rs1;
            } else {
#pragma unroll
                for (int j = 0; j < 4; j++){
                    pf[mt][j][0] = packh2(__expf(sa[mt][2*j][0] - mplv[mt][0]),
                                          __expf(sa[mt][2*j][1] - mplv[mt][0]));
                    pf[mt][j][1] = packh2(__expf(sa[mt][2*j][2] - mplv[mt][1]),
                                          __expf(sa[mt][2*j][3] - mplv[mt][1]));
                    pf[mt][j][2] = packh2(__expf(sa[mt][2*j+1][0] - mplv[mt][0]),
                                          __expf(sa[mt][2*j+1][1] - mplv[mt][0]));
                    pf[mt][j][3] = packh2(__expf(sa[mt][2*j+1][2] - mplv[mt][1]),
                                          __expf(sa[mt][2*j+1][3] - mplv[mt][1]));
                }
            }
        }

#pragma unroll
        for (int kf = 0; kf < 4; kf++){
            uint32_t vf[8][2];
#pragma unroll
            for (int p = 0; p < 4; p++){
                uint32_t a = sv + ((kf*16 + (lane & 7) + ((lane >> 3) & 1)*8)*QS
                                   + p*16 + (lane >> 4)*8)*2;
                ldm4t(vf[2*p][0], vf[2*p][1], vf[2*p+1][0], vf[2*p+1][1], a);
            }
#pragma unroll
            for (int mt = 0; mt < 2; mt++)
#pragma unroll
            for (int nf = 0; nf < 8; nf++)
                mma16(ya[mt][nf], pf[mt][kf], vf[nf]);
        }
    }

    // ---- tail: key 576 (rank-1) ----
    {
        const __half2* kt2 = (const __half2*)(smh + TAILB/2);
        const __half2* vt2 = kt2 + 32;
#pragma unroll
        for (int mt = 0; mt < 2; mt++){
            float s0v = 0.f, s1v = 0.f;
#pragma unroll
            for (int kf = 0; kf < 4; kf++){
                uint32_t q0, q1, q2, q3;
                if (FIRST){
                    ldm4(q0, q1, q2, q3, qaddr(mt, kf));
                } else {
                    q0 = qf[mt][kf][0]; q1 = qf[mt][kf][1];
                    q2 = qf[mt][kf][2]; q3 = qf[mt][kf][3];
                }
                float2 klo = __half22float2(kt2[kf*8 + t]);
                float2 khi = __half22float2(kt2[kf*8 + 4 + t]);
                float2 q0l = h2f(q0), q1l = h2f(q1);
                float2 q0h = h2f(q2), q1h = h2f(q3);
                s0v += q0l.x*klo.x + q0l.y*klo.y + q0h.x*khi.x + q0h.y*khi.y;
                s1v += q1l.x*klo.x + q1l.y*klo.y + q1h.x*khi.x + q1h.y*khi.y;
            }
            s0v += __shfl_xor_sync(~0u, s0v, 1); s0v += __shfl_xor_sync(~0u, s0v, 2);
            s1v += __shfl_xor_sync(~0u, s1v, 1); s1v += __shfl_xor_sync(~0u, s1v, 2);

            if (FIRST){
                float mn0 = fmaxf(mr[mt][0], s0v), mn1 = fmaxf(mr[mt][1], s1v);
                float sc0 = __expf(mr[mt][0] - mn0), sc1 = __expf(mr[mt][1] - mn1);
                float p0 = __expf(s0v - mn0), p1 = __expf(s1v - mn1);
                l[mt][0] = l[mt][0]*sc0 + p0; l[mt][1] = l[mt][1]*sc1 + p1;
#pragma unroll
                for (int nf = 0; nf < 8; nf++){
                    float2 v2 = __half22float2(vt2[nf*4 + t]);
                    ya[mt][nf][0] = ya[mt][nf][0]*sc0 + p0*v2.x;
                    ya[mt][nf][1] = ya[mt][nf][1]*sc0 + p0*v2.y;
                    ya[mt][nf][2] = ya[mt][nf][2]*sc1 + p1*v2.x;
                    ya[mt][nf][3] = ya[mt][nf][3]*sc1 + p1*v2.y;
                }
                if (t == 0){
                    mpl[m0 + wr + mt*16 + g]     = mn0 + __logf(l[mt][0]);
                    mpl[m0 + wr + mt*16 + g + 8] = mn1 + __logf(l[mt][1]);
                }
            } else {
                float p0 = __expf(s0v - mplv[mt][0]), p1 = __expf(s1v - mplv[mt][1]);
#pragma unroll
                for (int nf = 0; nf < 8; nf++){
                    float2 v2 = __half22float2(vt2[nf*4 + t]);
                    ya[mt][nf][0] += p0*v2.x; ya[mt][nf][1] += p0*v2.y;
                    ya[mt][nf][2] += p1*v2.x; ya[mt][nf][3] += p1*v2.y;
                }
            }
        }
    }
    __syncthreads();

    float* st = (float*)smh;
#pragma unroll
    for (int mt = 0; mt < 2; mt++){
        float inv0 = FIRST ? (1.f / l[mt][0]) : 1.f;
        float inv1 = FIRST ? (1.f / l[mt][1]) : 1.f;
#pragma unroll
        for (int nf = 0; nf < 8; nf++){
            int d = nf*8 + t*2;
            st[(wr + mt*16 + g)*68 + d]         = ya[mt][nf][0]*inv0;
            st[(wr + mt*16 + g)*68 + d + 1]     = ya[mt][nf][1]*inv0;
            st[(wr + mt*16 + g + 8)*68 + d]     = ya[mt][nf][2]*inv1;
            st[(wr + mt*16 + g + 8)*68 + d + 1] = ya[mt][nf][3]*inv1;
        }
    }
    __syncthreads();
}

// K2: Y = softmax(qk) @ v -> g_Yh + g_Yf + g_mpl. grid (5, 192), 128 threads
__global__ void __launch_bounds__(128, 3) k_av_f(){
    extern __shared__ __align__(16) __half dsm[];
    int tid = threadIdx.x;
    int m0 = blockIdx.x*128, bh = blockIdx.y;
    size_t ob = (size_t)bh*NP*HD;
    flash_core<true>(dsm, g_q + ob, g_k + ob, g_v + ob, g_mpl + (size_t)bh*NP, m0, tid);

    const float* src = (const float*)dsm + tid*68;
    size_t o = ob + (size_t)(m0 + tid)*HD;
#pragma unroll
    for (int i = 0; i < 16; i++)
        ((float4*)(g_Yf + o))[i] = ((const float4*)src)[i];
#pragma unroll
    for (int i = 0; i < 8; i++){
        uint4 u;
        u.x = packh2(src[i*8+0], src[i*8+1]);
        u.y = packh2(src[i*8+2], src[i*8+3]);
        u.z = packh2(src[i*8+4], src[i*8+5]);
        u.w = packh2(src[i*8+6], src[i*8+7]);
        ((uint4*)(g_Yh + o))[i] = u;
    }
}

// K3: Z = softmax(qk) @ Y; hb = (1-2b)Y + 3b*Z. grid (5, 192), 128 threads
__global__ void __launch_bounds__(128, 3) k_ay_f(const float* __restrict__ lamb){
    extern __shared__ __align__(16) __half dsm[];
    int tid = threadIdx.x;
    int m0 = blockIdx.x*128, bh = blockIdx.y;
    int b = bh / HH, h = bh - b*HH;
    size_t ob = (size_t)bh*NP*HD;
    flash_core<false>(dsm, g_q + ob, g_k + ob, g_Yh + ob, g_mpl + (size_t)bh*NP, m0, tid);

    float beta = lamb[h];
    float c0 = 1.f - 2.f*beta, c1 = 3.f*beta;
    int tok = m0 + tid;
    if (tok < NN){
        const float* zs = (const float*)dsm + tid*68;
        const float* yf = g_Yf + ob + (size_t)tok*HD;
        __half* dst = g_hb + ((size_t)(b*NN + tok))*CC + h*64;
#pragma unroll
        for (int i = 0; i < 8; i++){
            uint4 u;
            u.x = packh2(c0*yf[i*8+0] + c1*zs[i*8+0], c0*yf[i*8+1] + c1*zs[i*8+1]);
            u.y = packh2(c0*yf[i*8+2] + c1*zs[i*8+2], c0*yf[i*8+3] + c1*zs[i*8+3]);
            u.z = packh2(c0*yf[i*8+4] + c1*zs[i*8+4], c0*yf[i*8+5] + c1*zs[i*8+5]);
            u.w = packh2(c0*yf[i*8+6] + c1*zs[i*8+6], c0*yf[i*8+7] + c1*zs[i*8+7]);
            ((uint4*)dst)[i] = u;
        }
    }
}

// K4: out = hb @ Wp^T + bp (NT, fp32 out), 128 threads, staged epilogue.
// grid (6, 73)
#define SP 132
#define PROJ_SMEM (128*SP*4)   // 67584
__global__ void __launch_bounds__(128)
k_proj(const float* __restrict__ bp, float* __restrict__ out){
    extern __shared__ __align__(16) __half dsm[];
    int tid = threadIdx.x, lane = tid & 31, wid = tid >> 5;
    int wm = wid >> 1, wn = wid & 1, g = lane >> 2, t = lane & 3;
    int m0 = blockIdx.y*128, n0 = blockIdx.x*128;

    float acc[4][8][4] = {};
    gemm_nt_h(g_hb, CC, m0, MX, g_wp, CC, n0, CC, dsm, acc, tid);

    float* st = (float*)dsm;
#pragma unroll
    for (int mt = 0; mt < 4; mt++)
#pragma unroll
    for (int nf = 0; nf < 8; nf++){
        int col = wn*64 + nf*8 + t*2;
        float b0 = bp[n0 + col], b1 = bp[n0 + col + 1];
        int row0 = wm*64 + mt*16 + g;
#pragma unroll
        for (int rr = 0; rr < 2; rr++){
            st[(row0 + rr*8)*SP + col]     = acc[mt][nf][rr*2]   + b0;
            st[(row0 + rr*8)*SP + col + 1] = acc[mt][nf][rr*2+1] + b1;
        }
    }
    __syncthreads();

#pragma unroll
    for (int i = 0; i < 32; i++){
        int e = tid + i*128;
        int r = e >> 5, c = e & 31;
        int gm = m0 + r;
        if (gm >= MX) continue;
        *(float4*)&out[(size_t)gm*CC + n0 + c*4] = *(const float4*)&st[r*SP + c*4];
    }
}

// ======================== host launcher ========================
extern "C" void kernel_launch(void* const* d_in, const int* in_sizes, int n_in,
                              void* d_out, int out_size)
{
    const float* x    = (const float*)d_in[0];
    const float* Wq   = (const float*)d_in[1];
    const float* Wk   = (const float*)d_in[2];
    const float* Wv   = (const float*)d_in[3];
    const float* Wp   = (const float*)d_in[4];
    const float* bp   = (const float*)d_in[5];
    const float* lamb = (const float*)d_in[6];
    float* out = (float*)d_out;

    static bool attr_done = false;
    if (!attr_done){
        cudaFuncSetAttribute(k_qkv,  cudaFuncAttributeMaxDynamicSharedMemorySize, GEMM_SMEM);
        cudaFuncSetAttribute(k_proj, cudaFuncAttributeMaxDynamicSharedMemorySize, PROJ_SMEM);
        cudaFuncSetAttribute(k_av_f, cudaFuncAttributeMaxDynamicSharedMemorySize, FL_SMEM);
        cudaFuncSetAttribute(k_ay_f, cudaFuncAttributeMaxDynamicSharedMemorySize, FL_SMEM);
        attr_done = true;
    }

    k_cvt_all<<<(NCVT + 255)/256, 256>>>(x, Wq, Wk, Wv, Wp);
    k_qkv <<<dim3(CC/128, (MX + 127)/128, 3), 128, GEMM_SMEM>>>();
    k_av_f<<<dim3(NP/128, BH), 128, FL_SMEM>>>();
    k_ay_f<<<dim3(NP/128, BH), 128, FL_SMEM>>>(lamb);
    k_proj<<<dim3(CC/128, (MX + 127)/128), 128, PROJ_SMEM>>>(bp, out);
}